// round 2
// baseline (speedup 1.0000x reference)
#include <cuda_runtime.h>
#include <cstdint>

// Problem constants (fixed shapes for this problem instance)
#define BB 2
#define QQ 100
#define GG 10
#define TT 5
#define HH 128
#define WW 128
#define NC 41
#define PITCH 129   // padded SMEM row pitch (conflict-free column access)

// Scratch (no cudaMalloc allowed)
__device__ int4   d_boxes[BB * GG * TT];                 // y0,y1,x0,x1 per (b,g,t)
__device__ float4 d_part[BB * QQ * TT * GG];             // Ny, Sy, Nx, Sx per (b,q,t,g)

__device__ __forceinline__ float sigmoidf_fast(float x) {
    return 1.0f / (1.0f + __expf(-x));
}

// ---------------------------------------------------------------------------
// Kernel 1: per-(b,g,t) bounding boxes from binary box masks.
// grid = B*G*T blocks, 128 threads (one per row).
// ---------------------------------------------------------------------------
__global__ __launch_bounds__(128) void box_kernel(const float* __restrict__ bm) {
    __shared__ int sy0[128], sy1[128], sx0[128], sx1[128];
    const int tid = threadIdx.x;
    const float* row = bm + (size_t)blockIdx.x * (HH * WW) + (size_t)tid * WW;

    int first = WW, last = -1;
    #pragma unroll 4
    for (int w = 0; w < WW; w += 4) {
        float4 v = *reinterpret_cast<const float4*>(row + w);
        if (v.x > 0.5f) { if (first == WW) first = w;     last = w;     }
        if (v.y > 0.5f) { if (first == WW) first = w + 1; last = w + 1; }
        if (v.z > 0.5f) { if (first == WW) first = w + 2; last = w + 2; }
        if (v.w > 0.5f) { if (first == WW) first = w + 3; last = w + 3; }
    }
    const bool any = (last >= 0);
    sy0[tid] = any ? tid : HH;
    sy1[tid] = any ? tid : -1;
    sx0[tid] = first;          // WW if row empty
    sx1[tid] = last;           // -1 if row empty
    __syncthreads();

    if (tid == 0) {
        int y0 = HH, y1 = -1, x0 = WW, x1 = -1;
        for (int i = 0; i < HH; ++i) {
            y0 = min(y0, sy0[i]); y1 = max(y1, sy1[i]);
            x0 = min(x0, sx0[i]); x1 = max(x1, sx1[i]);
        }
        int4 o = (y1 < 0) ? make_int4(0, 0, 0, 0)
                          : make_int4(y0, y1 + 1, x0, x1 + 1);
        d_boxes[blockIdx.x] = o;
    }
}

// ---------------------------------------------------------------------------
// Kernel 2: main reduction. grid = B*Q*T blocks, 256 threads.
// Streams the (H,W) tile once, computes:
//   rowmax_full (folded into global load via warp shuffles),
//   colmax_full (SMEM, padded -> conflict-free),
//   per-g box-restricted row/col maxes,
// then emits (Ny, Sy, Nx, Sx) partials per g. All reductions are
// fixed-order shuffle trees -> bitwise deterministic.
// ---------------------------------------------------------------------------
__global__ __launch_bounds__(256) void main_kernel(const float* __restrict__ pm) {
    __shared__ float tile[HH * PITCH];
    __shared__ float rowm[HH];          // raw rowmax, then sigmoided in-place
    __shared__ float colm[WW];          // sigmoided colmax
    __shared__ float colpart[2][WW];
    __shared__ float sums[2];           // sumY, sumX

    const int blk  = blockIdx.x;        // (b*Q + q)*T + t
    const int t    = blk % TT;
    const int bq   = blk / TT;          // b*Q + q
    const int b    = bq / QQ;
    const int tid  = threadIdx.x;
    const int lane = tid & 31;
    const int wid  = tid >> 5;

    // ---- load tile + fold row maxes into the load ----
    const float4* src = reinterpret_cast<const float4*>(pm + (size_t)blk * (HH * WW));
    #pragma unroll 4
    for (int j = 0; j < 16; ++j) {
        const int v   = j * 256 + tid;     // float4 index; 32 per row
        const int row = v >> 5;            // = j*8 + wid  (warp == one row)
        const int cw  = (v & 31) * 4;      // = lane*4
        float4 d = src[v];
        float* dst = &tile[row * PITCH + cw];
        dst[0] = d.x; dst[1] = d.y; dst[2] = d.z; dst[3] = d.w;
        float m = fmaxf(fmaxf(d.x, d.y), fmaxf(d.z, d.w));
        #pragma unroll
        for (int o = 16; o >= 1; o >>= 1) m = fmaxf(m, __shfl_xor_sync(0xffffffffu, m, o));
        if (lane == 0) rowm[row] = m;      // raw max of this row
    }
    __syncthreads();

    // ---- column maxes: two 64-row halves per column ----
    {
        const int col = tid & 127, half = tid >> 7;
        const int h0 = half * 64;
        float m = -1e30f;
        #pragma unroll 8
        for (int h = h0; h < h0 + 64; ++h) m = fmaxf(m, tile[h * PITCH + col]);
        colpart[half][col] = m;
    }
    __syncthreads();
    if (tid < 128) {
        colm[tid] = sigmoidf_fast(fmaxf(colpart[0][tid], colpart[1][tid]));
    } else {
        const int r = tid - 128;
        rowm[r] = sigmoidf_fast(rowm[r]);
    }
    __syncthreads();

    // ---- full sums of sigmoided row/col maxes ----
    if (wid < 2) {
        const float* arr = (wid == 0) ? rowm : colm;
        float s = arr[lane] + arr[lane + 32] + arr[lane + 64] + arr[lane + 96];
        #pragma unroll
        for (int o = 16; o >= 1; o >>= 1) s += __shfl_xor_sync(0xffffffffu, s, o);
        if (lane == 0) sums[wid] = s;
    }
    __syncthreads();

    const float sumY = sums[0];
    const float sumX = sums[1];

    // ---- per-target box-restricted reductions (one warp per g) ----
    for (int g = wid; g < GG; g += 8) {
        const int4 bx = d_boxes[(b * GG + g) * TT + t];  // y0,y1,x0,x1

        float Ny = 0.f, Ry = 0.f;
        for (int h = bx.x + lane; h < bx.y; h += 32) {
            const float* rp = &tile[h * PITCH];
            float m = -1e30f;
            for (int w = bx.z; w < bx.w; ++w) m = fmaxf(m, rp[w]);
            Ny += sigmoidf_fast(m);
            Ry += rowm[h];
        }
        float Nx = 0.f, Rx = 0.f;
        for (int w = bx.z + lane; w < bx.w; w += 32) {
            float m = -1e30f;
            for (int h = bx.x; h < bx.y; ++h) m = fmaxf(m, tile[h * PITCH + w]);
            Nx += sigmoidf_fast(m);
            Rx += colm[w];
        }
        #pragma unroll
        for (int o = 16; o >= 1; o >>= 1) {
            Ny += __shfl_xor_sync(0xffffffffu, Ny, o);
            Ry += __shfl_xor_sync(0xffffffffu, Ry, o);
            Nx += __shfl_xor_sync(0xffffffffu, Nx, o);
            Rx += __shfl_xor_sync(0xffffffffu, Rx, o);
        }
        if (lane == 0) {
            float4 o;
            o.x = Ny;
            o.y = Ny + sumY - Ry;   // Sy
            o.z = Nx;
            o.w = Nx + sumX - Rx;   // Sx
            d_part[blk * GG + g] = o;
        }
    }
}

// ---------------------------------------------------------------------------
// Kernel 3: finalize. 2000 threads: softmax gather + dice assembly.
// tgt_ids is int32 (JAX x64 disabled downcasts the requested int64).
// ---------------------------------------------------------------------------
__global__ __launch_bounds__(256) void final_kernel(
    const float* __restrict__ logits,
    const int* __restrict__ tgt_ids,
    float* __restrict__ out)
{
    const int idx = blockIdx.x * blockDim.x + threadIdx.x;
    if (idx >= BB * QQ * GG) return;
    const int g  = idx % GG;
    const int bq = idx / GG;       // b*Q + q
    const int b  = bq / QQ;

    // class cost: -softmax(logits[b,q])[tgt_ids[b,g]]
    const float* lg = logits + (size_t)bq * NC;
    float mx = lg[0];
    #pragma unroll
    for (int c = 1; c < NC; ++c) mx = fmaxf(mx, lg[c]);
    float se = 0.f;
    #pragma unroll
    for (int c = 0; c < NC; ++c) se += __expf(lg[c] - mx);
    const int cls = tgt_ids[b * GG + g];
    const float prob = __expf(lg[cls] - mx) / se;

    // dice over (T, H) and (T, W)
    float Ny = 0.f, Sy = 0.f, Nx = 0.f, Sx = 0.f, Ty = 0.f, Tx = 0.f;
    #pragma unroll
    for (int t = 0; t < TT; ++t) {
        float4 p = d_part[(bq * TT + t) * GG + g];
        Ny += p.x; Sy += p.y; Nx += p.z; Sx += p.w;
        int4 bx = d_boxes[(b * GG + g) * TT + t];
        Ty += (float)(bx.y - bx.x);
        Tx += (float)(bx.w - bx.z);
    }
    const float dice_y = 1.f - (2.f * Ny + 1.f) / (Sy + Ty + 1.f);
    const float dice_x = 1.f - (2.f * Nx + 1.f) / (Sx + Tx + 1.f);

    out[idx] = 2.f * (-prob) + 5.f * (dice_y + dice_x);
}

// ---------------------------------------------------------------------------
extern "C" void kernel_launch(void* const* d_in, const int* in_sizes, int n_in,
                              void* d_out, int out_size) {
    const float* pred_logits = (const float*)d_in[0];      // (B,Q,C)
    const float* pred_masks  = (const float*)d_in[1];      // (B,Q,T,H,W)
    const float* box_masks   = (const float*)d_in[2];      // (B,G,T,H,W)
    const int*   tgt_ids     = (const int*)d_in[3];        // (B,G) int32
    float* out = (float*)d_out;                            // (B,Q,G)

    box_kernel<<<BB * GG * TT, 128>>>(box_masks);
    main_kernel<<<BB * QQ * TT, 256>>>(pred_masks);
    final_kernel<<<(BB * QQ * GG + 255) / 256, 256>>>(pred_logits, tgt_ids, out);
}

// round 3
// speedup vs baseline: 1.1790x; 1.1790x over previous
#include <cuda_runtime.h>
#include <cstdint>

#define BB 2
#define QQ 100
#define GG 10
#define TT 5
#define HH 128
#define WW 128
#define NC 41

// Scratch (no cudaMalloc allowed)
__device__ int4   d_boxes[BB * GG * TT];                 // y0,y1,x0,x1 per (b,g,t)
__device__ float4 d_part[BB * QQ * TT * GG];             // Ny, Sy, Nx, Sx per (b,q,t,g)

__device__ __forceinline__ float sigmoidf_fast(float x) {
    return 1.0f / (1.0f + __expf(-x));
}

// XOR-swizzled tile addressing: float4 index for (row h, float4-col w4).
// Conflict-free for: row-major float4 st/ld (lane=w4, same h), column access
// (lanes = consecutive cols, same h), and lanes-across-rows (h varies per lane).
__device__ __forceinline__ int sw4(int h, int w4) { return (h << 5) + (w4 ^ (h & 31)); }
__device__ __forceinline__ float tile_ld(const float* t, int h, int w) {
    return t[(sw4(h, w >> 2) << 2) + (w & 3)];
}

// ---------------------------------------------------------------------------
// Kernel 1: bounding boxes. grid = B*G*T, 256 threads.
// k-major coalesced float4 loads; branchless index min/max; shuffle reduce.
// ---------------------------------------------------------------------------
__global__ __launch_bounds__(256) void box_kernel(const float* __restrict__ bm) {
    __shared__ int4 wred[8];
    const int tid  = threadIdx.x;
    const int lane = tid & 31;
    const int wid  = tid >> 5;
    const float4* src = reinterpret_cast<const float4*>(bm + (size_t)blockIdx.x * (HH * WW));

    const int c0 = (tid & 31) * 4;     // this thread's 4 fixed columns
    int ymin = HH, ymax = -1, xmin = WW, xmax = -1;

    #pragma unroll
    for (int k = 0; k < 16; ++k) {
        const int v   = k * 256 + tid;
        const int row = v >> 5;        // = k*8 + wid
        float4 d = src[v];
        const bool f0 = d.x > 0.5f, f1 = d.y > 0.5f, f2 = d.z > 0.5f, f3 = d.w > 0.5f;
        xmin = min(xmin, f0 ? c0     : WW);
        xmin = min(xmin, f1 ? c0 + 1 : WW);
        xmin = min(xmin, f2 ? c0 + 2 : WW);
        xmin = min(xmin, f3 ? c0 + 3 : WW);
        xmax = max(xmax, f0 ? c0     : -1);
        xmax = max(xmax, f1 ? c0 + 1 : -1);
        xmax = max(xmax, f2 ? c0 + 2 : -1);
        xmax = max(xmax, f3 ? c0 + 3 : -1);
        const bool any = f0 | f1 | f2 | f3;
        ymin = min(ymin, any ? row : HH);
        ymax = max(ymax, any ? row : -1);
    }
    #pragma unroll
    for (int o = 16; o >= 1; o >>= 1) {
        ymin = min(ymin, __shfl_xor_sync(0xffffffffu, ymin, o));
        ymax = max(ymax, __shfl_xor_sync(0xffffffffu, ymax, o));
        xmin = min(xmin, __shfl_xor_sync(0xffffffffu, xmin, o));
        xmax = max(xmax, __shfl_xor_sync(0xffffffffu, xmax, o));
    }
    if (lane == 0) wred[wid] = make_int4(ymin, ymax, xmin, xmax);
    __syncthreads();
    if (wid == 0) {
        int4 r = wred[lane & 7];
        #pragma unroll
        for (int o = 4; o >= 1; o >>= 1) {
            r.x = min(r.x, __shfl_xor_sync(0xffffffffu, r.x, o));
            r.y = max(r.y, __shfl_xor_sync(0xffffffffu, r.y, o));
            r.z = min(r.z, __shfl_xor_sync(0xffffffffu, r.z, o));
            r.w = max(r.w, __shfl_xor_sync(0xffffffffu, r.w, o));
        }
        if (lane == 0) {
            d_boxes[blockIdx.x] = (r.y < 0) ? make_int4(0, 0, 0, 0)
                                            : make_int4(r.x, r.y + 1, r.z, r.w + 1);
        }
    }
}

// ---------------------------------------------------------------------------
// Kernel 2: main reduction. grid = B*Q*T, 256 threads, 3 CTAs/SM.
// ---------------------------------------------------------------------------
__global__ __launch_bounds__(256, 3) void main_kernel(const float* __restrict__ pm) {
    __shared__ float4 tile4[HH * 32];      // 64 KB, XOR-swizzled
    __shared__ float4 colpart4[8 * 32];    // per-warp-rowgroup column partial maxes
    __shared__ float  rowm[HH];            // raw rowmax -> sigmoided in place
    __shared__ float  colm[WW];            // sigmoided colmax
    __shared__ float  sums[2];
    const float* tile = reinterpret_cast<const float*>(tile4);
    float* colpart = reinterpret_cast<float*>(colpart4);

    const int blk  = blockIdx.x;           // (b*Q + q)*T + t
    const int t    = blk % TT;
    const int bq   = blk / TT;
    const int b    = bq / QQ;
    const int tid  = threadIdx.x;
    const int lane = tid & 31;
    const int wid  = tid >> 5;

    // ---- phase 1: stream tile; fold row maxes (shfl) + col maxes (regs) ----
    const float4* src = reinterpret_cast<const float4*>(pm + (size_t)blk * (HH * WW));
    float4 cm = make_float4(-1e30f, -1e30f, -1e30f, -1e30f);   // cols lane*4..+3
    float4 v[8];
    #pragma unroll
    for (int batch = 0; batch < 2; ++batch) {
        #pragma unroll
        for (int j2 = 0; j2 < 8; ++j2) v[j2] = src[(batch * 8 + j2) * 256 + tid];
        #pragma unroll
        for (int j2 = 0; j2 < 8; ++j2) {
            const int row = (batch * 8 + j2) * 8 + wid;
            float4 d = v[j2];
            tile4[sw4(row, lane)] = d;                          // conflict-free STS.128
            cm.x = fmaxf(cm.x, d.x); cm.y = fmaxf(cm.y, d.y);
            cm.z = fmaxf(cm.z, d.z); cm.w = fmaxf(cm.w, d.w);
            float m = fmaxf(fmaxf(d.x, d.y), fmaxf(d.z, d.w));
            #pragma unroll
            for (int o = 16; o >= 1; o >>= 1) m = fmaxf(m, __shfl_xor_sync(0xffffffffu, m, o));
            if (lane == 0) rowm[row] = m;                      // raw row max
        }
    }
    colpart4[wid * 32 + lane] = cm;                            // conflict-free
    __syncthreads();

    // ---- combine col partials + sigmoid row/col maxes ----
    if (tid < 128) {
        float m = colpart[tid];
        #pragma unroll
        for (int w = 1; w < 8; ++w) m = fmaxf(m, colpart[w * 128 + tid]);
        colm[tid] = sigmoidf_fast(m);
    } else {
        const int r = tid - 128;
        rowm[r] = sigmoidf_fast(rowm[r]);
    }
    __syncthreads();

    // ---- full sums of sigmoided row/col maxes ----
    if (wid < 2) {
        const float* arr = (wid == 0) ? rowm : colm;
        float s = arr[lane] + arr[lane + 32] + arr[lane + 64] + arr[lane + 96];
        #pragma unroll
        for (int o = 16; o >= 1; o >>= 1) s += __shfl_xor_sync(0xffffffffu, s, o);
        if (lane == 0) sums[wid] = s;
    }
    __syncthreads();
    const float sumY = sums[0];
    const float sumX = sums[1];

    // ---- per-target box-restricted reductions (one warp per g) ----
    for (int g = wid; g < GG; g += 8) {
        const int4 bx = d_boxes[(b * GG + g) * TT + t];  // y0,y1,x0,x1

        // row maxes over x-range: lane ℓ handles rows y0+ℓ, y0+ℓ+32, ...
        float Ny = 0.f, Ry = 0.f;
        const int w40 = bx.z >> 2;
        const int w41 = (bx.w - 1) >> 2;                 // bx.w>=1 when non-empty
        for (int h = bx.x + lane; h < bx.y; h += 32) {
            const int hs = h << 5, hx = h & 31;
            float m = -1e30f;
            for (int w4 = w40; w4 <= w41; ++w4) {
                float4 d = tile4[hs + (w4 ^ hx)];
                const int wb = w4 << 2;
                m = fmaxf(m, (wb     >= bx.z && wb     < bx.w) ? d.x : -1e30f);
                m = fmaxf(m, (wb + 1 >= bx.z && wb + 1 < bx.w) ? d.y : -1e30f);
                m = fmaxf(m, (wb + 2 >= bx.z && wb + 2 < bx.w) ? d.z : -1e30f);
                m = fmaxf(m, (wb + 3 >= bx.z && wb + 3 < bx.w) ? d.w : -1e30f);
            }
            Ny += sigmoidf_fast(m);
            Ry += rowm[h];
        }

        // col maxes over y-range: lane ℓ handles cols x0+ℓ, x0+ℓ+32, ...
        float Nx = 0.f, Rx = 0.f;
        for (int w = bx.z + lane; w < bx.w; w += 32) {
            float m0 = -1e30f, m1 = -1e30f;
            int h = bx.x;
            for (; h + 1 < bx.y; h += 2) {
                m0 = fmaxf(m0, tile_ld(tile, h, w));
                m1 = fmaxf(m1, tile_ld(tile, h + 1, w));
            }
            if (h < bx.y) m0 = fmaxf(m0, tile_ld(tile, h, w));
            Nx += sigmoidf_fast(fmaxf(m0, m1));
            Rx += colm[w];
        }

        #pragma unroll
        for (int o = 16; o >= 1; o >>= 1) {
            Ny += __shfl_xor_sync(0xffffffffu, Ny, o);
            Ry += __shfl_xor_sync(0xffffffffu, Ry, o);
            Nx += __shfl_xor_sync(0xffffffffu, Nx, o);
            Rx += __shfl_xor_sync(0xffffffffu, Rx, o);
        }
        if (lane == 0) {
            float4 o;
            o.x = Ny;
            o.y = Ny + sumY - Ry;   // Sy
            o.z = Nx;
            o.w = Nx + sumX - Rx;   // Sx
            d_part[blk * GG + g] = o;
        }
    }
}

// ---------------------------------------------------------------------------
// Kernel 3: finalize. softmax gather + dice assembly. tgt_ids is int32.
// ---------------------------------------------------------------------------
__global__ __launch_bounds__(256) void final_kernel(
    const float* __restrict__ logits,
    const int* __restrict__ tgt_ids,
    float* __restrict__ out)
{
    const int idx = blockIdx.x * blockDim.x + threadIdx.x;
    if (idx >= BB * QQ * GG) return;
    const int g  = idx % GG;
    const int bq = idx / GG;
    const int b  = bq / QQ;

    const float* lg = logits + (size_t)bq * NC;
    float mx = lg[0];
    #pragma unroll
    for (int c = 1; c < NC; ++c) mx = fmaxf(mx, lg[c]);
    float se = 0.f;
    #pragma unroll
    for (int c = 0; c < NC; ++c) se += __expf(lg[c] - mx);
    const int cls = tgt_ids[b * GG + g];
    const float prob = __expf(lg[cls] - mx) / se;

    float Ny = 0.f, Sy = 0.f, Nx = 0.f, Sx = 0.f, Ty = 0.f, Tx = 0.f;
    #pragma unroll
    for (int t = 0; t < TT; ++t) {
        float4 p = d_part[(bq * TT + t) * GG + g];
        Ny += p.x; Sy += p.y; Nx += p.z; Sx += p.w;
        int4 bx = d_boxes[(b * GG + g) * TT + t];
        Ty += (float)(bx.y - bx.x);
        Tx += (float)(bx.w - bx.z);
    }
    const float dice_y = 1.f - (2.f * Ny + 1.f) / (Sy + Ty + 1.f);
    const float dice_x = 1.f - (2.f * Nx + 1.f) / (Sx + Tx + 1.f);

    out[idx] = 2.f * (-prob) + 5.f * (dice_y + dice_x);
}

// ---------------------------------------------------------------------------
extern "C" void kernel_launch(void* const* d_in, const int* in_sizes, int n_in,
                              void* d_out, int out_size) {
    const float* pred_logits = (const float*)d_in[0];      // (B,Q,C)
    const float* pred_masks  = (const float*)d_in[1];      // (B,Q,T,H,W)
    const float* box_masks   = (const float*)d_in[2];      // (B,G,T,H,W)
    const int*   tgt_ids     = (const int*)d_in[3];        // (B,G) int32
    float* out = (float*)d_out;                            // (B,Q,G)

    box_kernel<<<BB * GG * TT, 256>>>(box_masks);
    main_kernel<<<BB * QQ * TT, 256>>>(pred_masks);
    final_kernel<<<(BB * QQ * GG + 255) / 256, 256>>>(pred_logits, tgt_ids, out);
}